// round 2
// baseline (speedup 1.0000x reference)
#include <cuda_runtime.h>
#include <math_constants.h>

#define N_IN   16384
#define NCONV  128
#define KMAX   11
#define TPB    256
#define CPB    16   // convs per block

__device__ __forceinline__ float warpReduceMax(float v) {
#pragma unroll
    for (int o = 16; o > 0; o >>= 1)
        v = fmaxf(v, __shfl_xor_sync(0xffffffffu, v, o));
    return v;
}
__device__ __forceinline__ int warpReduceSum(int v) {
#pragma unroll
    for (int o = 16; o > 0; o >>= 1)
        v += __shfl_xor_sync(0xffffffffu, v, o);
    return v;
}

// Read element c of an integer metadata array that may be int64 or int32.
__device__ __forceinline__ int meta_at(const void* arr, int c, bool is64) {
    if (is64) return (int)((const long long*)arr)[c];
    return ((const int*)arr)[c];
}

// Compute per-thread partial (max, neg-count) for one conv.
// xs: smem copy of x row, with xs[N_IN] == 0.0f sentinel for padding.
template <int K>
__device__ __forceinline__ void conv_feat(
    const float* __restrict__ xs,
    const float* __restrict__ wrow, float bias,
    int d, int p, int L,
    float& mx_out, int& neg_out)
{
    float w[K];
#pragma unroll
    for (int j = 0; j < K; j++) w[j] = wrow[j];
    int off[K];
#pragma unroll
    for (int j = 0; j < K; j++) off[j] = j * d;

    float mx = -CUDART_INF_F;
    int   neg = 0;
    const int tid = threadIdx.x;

    // middle zone [m_lo, m_hi): all K taps in-range (t>=p and t-p+(K-1)d <= N-1)
    const int m_lo = min(p, L);
    const int m_hi = max(m_lo, L - p);

    // ---- left edge: clamped taps ----
    for (int t = tid; t < m_lo; t += TPB) {
        float y = bias;
#pragma unroll
        for (int j = 0; j < K; j++) {
            int idx = t - p + off[j];
            unsigned ui = min((unsigned)idx, (unsigned)N_IN); // OOB -> sentinel
            y = fmaf(w[j], xs[ui], y);
        }
        mx = fmaxf(mx, y);
        neg += (int)(__float_as_uint(y) >> 31);
    }

    // ---- middle: no bounds checks (hot loop) ----
    for (int t = m_lo + tid; t < m_hi; t += TPB) {
        const float* xb = xs + (t - p);
        float y = bias;
#pragma unroll
        for (int j = 0; j < K; j++)
            y = fmaf(w[j], xb[off[j]], y);
        mx = fmaxf(mx, y);
        neg += (int)(__float_as_uint(y) >> 31);
    }

    // ---- right edge: clamped taps ----
    for (int t = m_hi + tid; t < L; t += TPB) {
        float y = bias;
#pragma unroll
        for (int j = 0; j < K; j++) {
            int idx = t - p + off[j];
            unsigned ui = min((unsigned)idx, (unsigned)N_IN);
            y = fmaf(w[j], xs[ui], y);
        }
        mx = fmaxf(mx, y);
        neg += (int)(__float_as_uint(y) >> 31);
    }

    mx_out = mx;
    neg_out = neg;
}

__global__ void __launch_bounds__(TPB)
feat_kernel(const float* __restrict__ x,
            const float* __restrict__ W,
            const float* __restrict__ B,
            const void* __restrict__ KS,
            const void* __restrict__ DS,
            const void* __restrict__ PS,
            float* __restrict__ out)
{
    extern __shared__ float xs[];   // N_IN + sentinel
    const int b = blockIdx.y;

    // Load x row into smem (float4 vectorized).
    {
        const float4* xr4 = (const float4*)(x + (size_t)b * N_IN);
        float4* xs4 = (float4*)xs;
        for (int i = threadIdx.x; i < N_IN / 4; i += TPB)
            xs4[i] = xr4[i];
        if (threadIdx.x == 0) xs[N_IN] = 0.0f;
    }

    __shared__ float rmax[TPB / 32];
    __shared__ int   rneg[TPB / 32];
    __syncthreads();

    // Detect int64 vs int32 metadata: kernel_sizes[0] in [7,11], so for int64
    // the second 32-bit word is 0; for int32 it is kernel_sizes[1] (>=7).
    const bool is64 = (((const int*)KS)[1] == 0);

    const int c0 = blockIdx.x * CPB;
    for (int c = c0; c < c0 + CPB; ++c) {
        const int k = meta_at(KS, c, is64);
        const int d = meta_at(DS, c, is64);
        const int p = meta_at(PS, c, is64);
        const int L = N_IN + 2 * p - d * (k - 1);

        const float* wrow = W + c * KMAX;
        const float bias  = B[c];

        float mx; int neg;
        if (k == 7)       conv_feat<7 >(xs, wrow, bias, d, p, L, mx, neg);
        else if (k == 9)  conv_feat<9 >(xs, wrow, bias, d, p, L, mx, neg);
        else              conv_feat<11>(xs, wrow, bias, d, p, L, mx, neg);

        // block reduction
        mx  = warpReduceMax(mx);
        neg = warpReduceSum(neg);
        const int warp = threadIdx.x >> 5;
        const int lane = threadIdx.x & 31;
        if (lane == 0) { rmax[warp] = mx; rneg[warp] = neg; }
        __syncthreads();
        if (threadIdx.x == 0) {
            float m = rmax[0]; int n = rneg[0];
#pragma unroll
            for (int i = 1; i < TPB / 32; i++) {
                m = fmaxf(m, rmax[i]);
                n += rneg[i];
            }
            const size_t base = (size_t)b * (2 * NCONV) + 2 * c;
            out[base]     = m;
            out[base + 1] = (float)(L - n) / (float)L;   // ppv = count(y>=0)/L
        }
        __syncthreads();   // protect rmax/rneg reuse for next conv
    }
}

extern "C" void kernel_launch(void* const* d_in, const int* in_sizes, int n_in,
                              void* d_out, int out_size)
{
    const float* x  = (const float*)d_in[0];
    const float* W  = (const float*)d_in[1];
    const float* B  = (const float*)d_in[2];
    const void*  KS = d_in[3];
    const void*  DS = d_in[4];
    const void*  PS = d_in[5];
    float* out = (float*)d_out;

    const int batch = in_sizes[0] / N_IN;   // 256

    const size_t smem = (N_IN + 16) * sizeof(float);  // row + sentinel + pad
    cudaFuncSetAttribute(feat_kernel,
                         cudaFuncAttributeMaxDynamicSharedMemorySize,
                         (int)smem);

    dim3 grid(NCONV / CPB, batch);
    feat_kernel<<<grid, TPB, smem>>>(x, W, B, KS, DS, PS, out);
}